// round 2
// baseline (speedup 1.0000x reference)
#include <cuda_runtime.h>

// ---------------------------------------------------------------------------
// MoE router: logits = X[16384,2048] @ W^T[2048,64]; top-2 (+softmax weights),
// full softmax mean per expert + top-1 counts -> Switch aux loss.
// Output layout (all f32): [0,32768) indices, [32768,65536) weights, [65536] aux.
// ---------------------------------------------------------------------------

#define TOKENS   16384
#define DDIM     2048
#define NEXP     64
#define BM       128
#define BK       32
#define NITERS   (DDIM / BK)        // 64
#define XTSTR    132                // padded token-stride of transposed X tile
#define WSTR     68                 // padded expert-stride of transposed W tile
#define WGT_OFF  (2 * TOKENS)
#define AUX_OFF  (4 * TOKENS)
#define AUX_W    0.01f

__device__ float g_probsum[NEXP];
__device__ int   g_cnt[NEXP];

__device__ __forceinline__ void fma2(unsigned long long& d,
                                     unsigned long long a,
                                     unsigned long long b) {
    asm("fma.rn.f32x2 %0, %1, %2, %0;" : "+l"(d) : "l"(a), "l"(b));
}

__device__ __forceinline__ unsigned long long dup2(float w) {
    unsigned long long r;
    asm("mov.b64 %0, {%1, %1};" : "=l"(r) : "f"(w));
    return r;
}

struct SmemT {
    union {
        struct { float xt[BK][XTSTR]; float wt[BK][WSTR]; } ml;   // mainloop tiles
        struct { float logits[BM][NEXP + 1]; } ep;                // epilogue
    } u;
    float tmax[BM];
    float tinv[BM];
    int   scnt[NEXP];
};

__global__ void zero_kernel() {
    int t = threadIdx.x;
    if (t < NEXP) { g_probsum[t] = 0.0f; g_cnt[t] = 0; }
}

__global__ void __launch_bounds__(256, 1)
router_kernel(const float* __restrict__ X, const float* __restrict__ W,
              float* __restrict__ out) {
    __shared__ SmemT s;
    const int tid = threadIdx.x;
    const int T0  = blockIdx.x * BM;

    if (tid < NEXP) s.scnt[tid] = 0;

    // 8 tokens x 4 experts per thread; token pairs packed as f32x2.
    unsigned long long acc[4][4];
#pragma unroll
    for (int j = 0; j < 4; ++j)
#pragma unroll
        for (int i = 0; i < 4; ++i) acc[j][i] = 0ull;

    const int tx = tid & 15;          // expert group
    const int ty = tid >> 4;          // token group
    const int e0 = tx * 4;
    const int t0 = ty * 8;

    // global-load register staging (next K-slab)
    float4 xr[4], wr[2];

    // --- prologue: load & store K-slab 0 ---
    {
        const int K0 = 0;
#pragma unroll
        for (int p = 0; p < 4; ++p) {
            int slot = tid + 256 * p;
            int r = slot >> 3;
            int c = (slot & 7) << 2;
            xr[p] = *(const float4*)(X + (size_t)(T0 + r) * DDIM + K0 + c);
        }
#pragma unroll
        for (int p = 0; p < 2; ++p) {
            int slot = tid + 256 * p;
            int e = slot >> 3;
            int c = (slot & 7) << 2;
            wr[p] = *(const float4*)(W + (size_t)e * DDIM + K0 + c);
        }
#pragma unroll
        for (int p = 0; p < 4; ++p) {
            int slot = tid + 256 * p;
            int r = slot >> 3;
            int c = (slot & 7) << 2;
            s.u.ml.xt[c + 0][r] = xr[p].x;
            s.u.ml.xt[c + 1][r] = xr[p].y;
            s.u.ml.xt[c + 2][r] = xr[p].z;
            s.u.ml.xt[c + 3][r] = xr[p].w;
        }
#pragma unroll
        for (int p = 0; p < 2; ++p) {
            int slot = tid + 256 * p;
            int e = slot >> 3;
            int c = (slot & 7) << 2;
            s.u.ml.wt[c + 0][e] = wr[p].x;
            s.u.ml.wt[c + 1][e] = wr[p].y;
            s.u.ml.wt[c + 2][e] = wr[p].z;
            s.u.ml.wt[c + 3][e] = wr[p].w;
        }
        __syncthreads();
    }

    // --- mainloop ---
    for (int it = 0; it < NITERS; ++it) {
        // issue global loads for next slab (latency hidden under compute)
        if (it + 1 < NITERS) {
            const int K0 = (it + 1) * BK;
#pragma unroll
            for (int p = 0; p < 4; ++p) {
                int slot = tid + 256 * p;
                int r = slot >> 3;
                int c = (slot & 7) << 2;
                xr[p] = *(const float4*)(X + (size_t)(T0 + r) * DDIM + K0 + c);
            }
#pragma unroll
            for (int p = 0; p < 2; ++p) {
                int slot = tid + 256 * p;
                int e = slot >> 3;
                int c = (slot & 7) << 2;
                wr[p] = *(const float4*)(W + (size_t)e * DDIM + K0 + c);
            }
        }

        // compute BK k-steps from smem
#pragma unroll
        for (int k = 0; k < BK; ++k) {
            ulonglong2 xa = *(const ulonglong2*)&s.u.ml.xt[k][t0];      // tokens t0..t0+3
            ulonglong2 xb = *(const ulonglong2*)&s.u.ml.xt[k][t0 + 4];  // tokens t0+4..t0+7
            float4 wq = *(const float4*)&s.u.ml.wt[k][e0];
            unsigned long long wd0 = dup2(wq.x);
            unsigned long long wd1 = dup2(wq.y);
            unsigned long long wd2 = dup2(wq.z);
            unsigned long long wd3 = dup2(wq.w);
            fma2(acc[0][0], xa.x, wd0); fma2(acc[0][1], xa.x, wd1);
            fma2(acc[0][2], xa.x, wd2); fma2(acc[0][3], xa.x, wd3);
            fma2(acc[1][0], xa.y, wd0); fma2(acc[1][1], xa.y, wd1);
            fma2(acc[1][2], xa.y, wd2); fma2(acc[1][3], xa.y, wd3);
            fma2(acc[2][0], xb.x, wd0); fma2(acc[2][1], xb.x, wd1);
            fma2(acc[2][2], xb.x, wd2); fma2(acc[2][3], xb.x, wd3);
            fma2(acc[3][0], xb.y, wd0); fma2(acc[3][1], xb.y, wd1);
            fma2(acc[3][2], xb.y, wd2); fma2(acc[3][3], xb.y, wd3);
        }

        __syncthreads();
        if (it + 1 < NITERS) {
#pragma unroll
            for (int p = 0; p < 4; ++p) {
                int slot = tid + 256 * p;
                int r = slot >> 3;
                int c = (slot & 7) << 2;
                s.u.ml.xt[c + 0][r] = xr[p].x;
                s.u.ml.xt[c + 1][r] = xr[p].y;
                s.u.ml.xt[c + 2][r] = xr[p].z;
                s.u.ml.xt[c + 3][r] = xr[p].w;
            }
#pragma unroll
            for (int p = 0; p < 2; ++p) {
                int slot = tid + 256 * p;
                int e = slot >> 3;
                int c = (slot & 7) << 2;
                s.u.ml.wt[c + 0][e] = wr[p].x;
                s.u.ml.wt[c + 1][e] = wr[p].y;
                s.u.ml.wt[c + 2][e] = wr[p].z;
                s.u.ml.wt[c + 3][e] = wr[p].w;
            }
            __syncthreads();
        }
    }

    // --- epilogue ---
    // dump accumulators to smem logits[token][expert]
#pragma unroll
    for (int j = 0; j < 4; ++j)
#pragma unroll
        for (int i = 0; i < 4; ++i) {
            union { unsigned long long u; float2 f; } cv;
            cv.u = acc[j][i];
            s.u.ep.logits[t0 + 2 * j + 0][e0 + i] = cv.f.x;
            s.u.ep.logits[t0 + 2 * j + 1][e0 + i] = cv.f.y;
        }
    __syncthreads();

    // per-token: top-2 (stable, lowest index on ties), full-softmax normalizer
    if (tid < BM) {
        const int t = tid;
        float m1 = -3.4e38f, m2 = -3.4e38f;
        int   i1 = 0, i2 = 0;
#pragma unroll 8
        for (int e = 0; e < NEXP; ++e) {
            float l = s.u.ep.logits[t][e];
            if (l > m1) { m2 = m1; i2 = i1; m1 = l; i1 = e; }
            else if (l > m2) { m2 = l; i2 = e; }
        }
        float sum = 0.0f;
#pragma unroll 8
        for (int e = 0; e < NEXP; ++e)
            sum += __expf(s.u.ep.logits[t][e] - m1);
        s.tmax[t] = m1;
        s.tinv[t] = 1.0f / sum;

        const int T = T0 + t;
        float d  = expf(m2 - m1);          // precise exp for the output weights
        float w1 = 1.0f / (1.0f + d);
        out[2 * T + 0] = (float)i1;
        out[2 * T + 1] = (float)i2;
        out[WGT_OFF + 2 * T + 0] = w1;
        out[WGT_OFF + 2 * T + 1] = d * w1;

        atomicAdd(&s.scnt[i1], 1);
    }
    __syncthreads();

    // column-wise probability sums: 4 row-groups x 64 experts
    {
        const int g = tid >> 6;           // 0..3
        const int e = tid & 63;
        float partial = 0.0f;
        const int tb = g * 32;
#pragma unroll 8
        for (int t = tb; t < tb + 32; ++t)
            partial += __expf(s.u.ep.logits[t][e] - s.tmax[t]) * s.tinv[t];
        atomicAdd(&g_probsum[e], partial);
    }
    if (tid < NEXP) atomicAdd(&g_cnt[tid], s.scnt[tid]);
}

__global__ void finalize_kernel(float* __restrict__ out) {
    __shared__ float red[NEXP];
    int e = threadIdx.x;
    red[e] = g_probsum[e] * (float)g_cnt[e];
    __syncthreads();
    if (e == 0) {
        float sacc = 0.0f;
        for (int i = 0; i < NEXP; ++i) sacc += red[i];
        const float invN = 1.0f / (float)TOKENS;
        out[AUX_OFF] = (float)NEXP * sacc * invN * invN * AUX_W;
    }
}

extern "C" void kernel_launch(void* const* d_in, const int* in_sizes, int n_in,
                              void* d_out, int out_size) {
    const float* X = (const float*)d_in[0];   // [4,4096,2048]
    const float* W = (const float*)d_in[1];   // [64,2048]
    float* out = (float*)d_out;               // 65537 f32

    zero_kernel<<<1, 64>>>();
    router_kernel<<<TOKENS / BM, 256>>>(X, W, out);
    finalize_kernel<<<1, NEXP>>>(out);
}